// round 16
// baseline (speedup 1.0000x reference)
#include <cuda_runtime.h>

// SlidingMean: out = (x - boxfilter_79x69(x)) / 5, SAME (zero) padding.
//  K1 : S8[n][g][c]  = sum of rows 8g..8g+7           (4 MB, float4)
//  K1b: S64[n][m][c] = sum of rows 8m..8m+63 (8-grid) (4 MB, from S8)
//  K2 : fused. Phase A interior init = S8@(hb-40) - x[hb-40] + S64@(hb-32)
//       + S8@(hb+32)  (4 loads instead of 16). Sliding fill, per-warp
//       block-cyclic register prefix scan, all-register shfl epilogue,
//       float4 LDG/STG, (512,3) + x prefetch (R15-proven).

#define HH 512
#define WW 512
#define NB 32
#define KH 79
#define KW 69
#define RH 39   // (KH-1)/2
#define RW 34   // (KW-1)/2
#define TH 16   // output rows per block in K2
#define NG 64   // 8-row groups per image

__device__ float g_s8 [NB * NG * WW];   // 4 MB
__device__ float g_s64[NB * 64 * WW];   // 4 MB (slot m = rows 8m..8m+63)

__device__ __forceinline__ float4 f4add(float4 a, float4 b) {
    return make_float4(a.x + b.x, a.y + b.y, a.z + b.z, a.w + b.w);
}
__device__ __forceinline__ float2 f2add(float2 a, float2 b) {
    return make_float2(a.x + b.x, a.y + b.y);
}
__device__ __forceinline__ float2 f2sub(float2 a, float2 b) {
    return make_float2(a.x - b.x, a.y - b.y);
}

// ---------------------------------------------------------------------------
// K1: 8-row group sums, float4. Grid = NB*NG/4 = 512 blocks of 512 threads.
// ---------------------------------------------------------------------------
__global__ __launch_bounds__(512) void s8_kernel(const float* __restrict__ x) {
    const int q = threadIdx.x >> 7;        // sub-group 0..3
    const int i = threadIdx.x & 127;       // float4 column
    const int g = (blockIdx.x << 2) + q;   // global group (n*NG + group)
    const float4* __restrict__ p = reinterpret_cast<const float4*>(x) + (g << 10) + i;
    float4 a = f4add(p[0 * 128], p[1 * 128]);
    float4 b = f4add(p[2 * 128], p[3 * 128]);
    a = f4add(a, p[4 * 128]);
    b = f4add(b, p[5 * 128]);
    a = f4add(a, p[6 * 128]);
    b = f4add(b, p[7 * 128]);
    reinterpret_cast<float4*>(g_s8)[(g << 7) + i] = f4add(a, b);
}

// ---------------------------------------------------------------------------
// K1b: S64 on the 8-row grid from S8. Grid = NB*16 blocks of 512 threads.
// ---------------------------------------------------------------------------
__global__ __launch_bounds__(512) void s64_kernel() {
    const int q = threadIdx.x >> 7;                 // 0..3
    const int i = threadIdx.x & 127;                // float4 column
    const int m = ((blockIdx.x & 15) << 2) + q;     // 8-grid slot 0..63
    const int n = blockIdx.x >> 4;                  // batch
    const float4* __restrict__ s8 =
        reinterpret_cast<const float4*>(g_s8) + (n << 13) + i;   // n*64*128
    // sum S8[m .. m+7], clamped (slots m>56 are never consumed)
    float4 a = f4add(s8[min(m + 0, 63) << 7], s8[min(m + 1, 63) << 7]);
    float4 b = f4add(s8[min(m + 2, 63) << 7], s8[min(m + 3, 63) << 7]);
    a = f4add(a, s8[min(m + 4, 63) << 7]);
    b = f4add(b, s8[min(m + 5, 63) << 7]);
    a = f4add(a, s8[min(m + 6, 63) << 7]);
    b = f4add(b, s8[min(m + 7, 63) << 7]);
    reinterpret_cast<float4*>(g_s64)[((n << 6) + m) * 128 + i] = f4add(a, b);
}

__global__ __launch_bounds__(512, 3) void sliding_mean_fused(const float* __restrict__ x,
                                                             float* __restrict__ out) {
    __shared__ float smemC[TH * WW];   // 32 KB, plain row-major

    const int blk = blockIdx.x;
    const int hc = blk & 31;           // 32 h-chunks of 16 rows
    const int n  = blk >> 5;           // batch
    const int h0 = hc * TH;
    const int t  = threadIdx.x;
    const int lane = t & 31;
    const int wrp  = t >> 5;

    const int gbase = n * (HH * WW);

    // ======================= Phase A (float2, two halves) ====================
    {
        const int halfid = t >> 8;         // 0: rows 0-7, 1: rows 8-15
        const int ht = t & 255;            // column-pair index (col = 2*ht)
        const int hb = h0 + (halfid << 3); // first row of this half

        const float2* __restrict__ xp2 =
            reinterpret_cast<const float2*>(x + gbase) + ht;           // row stride 256
        const float2* __restrict__ s8p2 =
            reinterpret_cast<const float2*>(g_s8 + (n << 15)) + ht;    // group stride 256
        const float2* __restrict__ s64p2 =
            reinterpret_cast<const float2*>(g_s64 + (n << 15)) + ht;   // slot stride 256
        float2* __restrict__ sm2 =
            reinterpret_cast<float2*>(smemC) + (halfid << 11) + ht;    // 8 rows * 256

        float2 s;
        const bool interior = (hb >= 40) && (hb <= 464);
        if (interior) {
            // window [hb-39, hb+39] = (S8@(hb-40) - x[hb-40]) + S64@(hb-32) + S8@(hb+32)
            float2 a0 = s8p2 [((hb - 40) >> 3) << 8];
            float2 a1 = xp2  [(hb - 40) << 8];
            float2 a2 = s64p2[((hb - 32) >> 3) << 8];
            float2 a3 = s8p2 [((hb + 32) >> 3) << 8];
            s = f2add(f2sub(a0, a1), f2add(a2, a3));

            const float2* __restrict__ pa = xp2 + ((hb + RH + 1) << 8);
            const float2* __restrict__ pb = xp2 + ((hb - RH) << 8);
            #pragma unroll
            for (int k = 0; k < 8; ++k) {
                sm2[k << 8] = s;
                s = f2add(s, f2sub(pa[k << 8], pb[k << 8]));
            }
        } else {
            int lo = hb - RH; if (lo < 0) lo = 0;
            int hi = hb + RH; if (hi > HH - 1) hi = HH - 1;
            const int glo = (lo + 7) >> 3;
            const int ghi = (hi + 1) >> 3;
            s = make_float2(0.f, 0.f);
            for (int r = lo; r < (glo << 3); ++r) s = f2add(s, xp2[r << 8]);
            for (int g = glo; g < ghi; ++g)       s = f2add(s, s8p2[g << 8]);
            for (int r = (ghi << 3); r <= hi; ++r) s = f2add(s, xp2[r << 8]);

            #pragma unroll
            for (int k = 0; k < 8; ++k) {
                sm2[k << 8] = s;
                int add = hb + k + RH + 1;
                int sb  = hb + k - RH;
                float2 a = (add < HH) ? xp2[add << 8] : make_float2(0.f, 0.f);
                float2 b = (sb >= 0)  ? xp2[sb << 8]  : make_float2(0.f, 0.f);
                s = f2add(s, f2sub(a, b));
            }
        }
    }
    __syncthreads();

    // ---- prefetch first half of epilogue x reads (overlaps the scan) --------
    const int rb4 = (gbase + (h0 + wrp) * WW) >> 2;   // float4 row base
    const float4* __restrict__ x4 = reinterpret_cast<const float4*>(x);
    float4* __restrict__ out4 = reinterpret_cast<float4*>(out);
    float4 xv0 = x4[rb4 + lane];
    float4 xv1 = x4[rb4 + lane + 32];

    // ========== Phase B: per-warp block-cyclic prefix scan (registers) =======
    // lane holds P at positions 128c + 4*lane + j  ->  p[4c + j]
    const unsigned FULL = 0xffffffffu;
    const float4* __restrict__ row4 =
        reinterpret_cast<const float4*>(smemC + (wrp << 9));

    float p[16];
    #pragma unroll
    for (int c = 0; c < 4; ++c) {
        float4 v = row4[lane + (c << 5)];
        p[c * 4 + 0] = v.x; p[c * 4 + 1] = v.y; p[c * 4 + 2] = v.z; p[c * 4 + 3] = v.w;
    }
    #pragma unroll
    for (int c = 0; c < 4; ++c) {
        p[c * 4 + 1] += p[c * 4 + 0];
        p[c * 4 + 2] += p[c * 4 + 1];
        p[c * 4 + 3] += p[c * 4 + 2];
    }
    float tot0 = p[3], tot1 = p[7], tot2 = p[11], tot3 = p[15];
    float i0 = tot0, i1 = tot1, i2 = tot2, i3 = tot3;
    #pragma unroll
    for (int off = 1; off < 32; off <<= 1) {
        float u0 = __shfl_up_sync(FULL, i0, off);
        float u1 = __shfl_up_sync(FULL, i1, off);
        float u2 = __shfl_up_sync(FULL, i2, off);
        float u3 = __shfl_up_sync(FULL, i3, off);
        if (lane >= off) { i0 += u0; i1 += u1; i2 += u2; i3 += u3; }
    }
    float B0 = __shfl_sync(FULL, i0, 31);
    float B1 = __shfl_sync(FULL, i1, 31);
    float B2 = __shfl_sync(FULL, i2, 31);
    float B3 = __shfl_sync(FULL, i3, 31);
    float o0 = i0 - tot0;
    float o1 = i1 - tot1 + B0;
    float o2 = i2 - tot2 + (B0 + B1);
    float o3 = i3 - tot3 + ((B0 + B1) + B2);
    p[0] += o0;  p[1] += o0;  p[2] += o0;  p[3] += o0;
    p[4] += o1;  p[5] += o1;  p[6] += o1;  p[7] += o1;
    p[8] += o2;  p[9] += o2;  p[10] += o2; p[11] += o2;
    p[12] += o3; p[13] += o3; p[14] += o3; p[15] += o3;
    const float total = ((B0 + B1) + B2) + B3;   // = P[511]

    // ===== Epilogue: register window taps via shfl + float4 x/out ============
    //   hi = P[w+34]  (pos>511 -> total)     lo = P[w-35]  (pos<0 -> 0)
    const float inv_cnt = 1.0f / (float)(KH * KW);
    const float inv_std = 0.2f;  // 1/5

    #pragma unroll
    for (int c = 0; c < 4; ++c) {
        // hi taps: j=0,1 -> src lane+8, reg j+2 ; j=2,3 -> src lane+9, reg j-2
        float h0s = (lane >= 8) ? p[4 * c + 2] : ((c < 3) ? p[4 * c + 6] : total);
        float h1s = (lane >= 8) ? p[4 * c + 3] : ((c < 3) ? p[4 * c + 7] : total);
        float h2s = (lane >= 9) ? p[4 * c + 0] : ((c < 3) ? p[4 * c + 4] : total);
        float h3s = (lane >= 9) ? p[4 * c + 1] : ((c < 3) ? p[4 * c + 5] : total);
        float hi0 = __shfl_sync(FULL, h0s, (lane + 8) & 31);
        float hi1 = __shfl_sync(FULL, h1s, (lane + 8) & 31);
        float hi2 = __shfl_sync(FULL, h2s, (lane + 9) & 31);
        float hi3 = __shfl_sync(FULL, h3s, (lane + 9) & 31);
        // lo taps: j=0,1,2 -> src lane-9, reg j+1 ; j=3 -> src lane-8, reg 0
        float l0s = (lane >= 23) ? ((c > 0) ? p[4 * c - 3] : 0.f) : p[4 * c + 1];
        float l1s = (lane >= 23) ? ((c > 0) ? p[4 * c - 2] : 0.f) : p[4 * c + 2];
        float l2s = (lane >= 23) ? ((c > 0) ? p[4 * c - 1] : 0.f) : p[4 * c + 3];
        float l3s = (lane >= 24) ? ((c > 0) ? p[4 * c - 4] : 0.f) : p[4 * c + 0];
        float lo0 = __shfl_sync(FULL, l0s, (lane - 9) & 31);
        float lo1 = __shfl_sync(FULL, l1s, (lane - 9) & 31);
        float lo2 = __shfl_sync(FULL, l2s, (lane - 9) & 31);
        float lo3 = __shfl_sync(FULL, l3s, (lane - 8) & 31);

        const float4 xv = (c == 0) ? xv0 : (c == 1) ? xv1 : x4[rb4 + lane + (c << 5)];
        float4 r;
        r.x = (xv.x - (hi0 - lo0) * inv_cnt) * inv_std;
        r.y = (xv.y - (hi1 - lo1) * inv_cnt) * inv_std;
        r.z = (xv.z - (hi2 - lo2) * inv_cnt) * inv_std;
        r.w = (xv.w - (hi3 - lo3) * inv_cnt) * inv_std;
        __stcs(&out4[rb4 + lane + (c << 5)], r);
    }
}

extern "C" void kernel_launch(void* const* d_in, const int* in_sizes, int n_in,
                              void* d_out, int out_size) {
    const float* x = (const float*)d_in[0];
    float* out = (float*)d_out;

    s8_kernel<<<NB * NG / 4, 512>>>(x);
    s64_kernel<<<NB * 16, 512>>>();
    sliding_mean_fused<<<NB * (HH / TH), 512>>>(x, out);
}

// round 17
// speedup vs baseline: 1.0890x; 1.0890x over previous
#include <cuda_runtime.h>

// SlidingMean: out = (x - boxfilter_79x69(x)) / 5, SAME (zero) padding.
//  K1: S8 8-row group sums, float4, 4 groups per 512-thr block.
//  K2: fused. Phase A: two 8-row halves, float2 columns, init from 9 S8 taps
//      + 7 x rows; fill fully software-pipelined (all 16 loads batched).
//      Phase B: per-warp block-cyclic register prefix scan. Epilogue:
//      all-register shfl window taps, float4 LDG/STG, full x prefetch.
//  (512,2): 64-reg budget buys max load MLP; 2 blocks/SM residency.

#define HH 512
#define WW 512
#define NB 32
#define KH 79
#define KW 69
#define RH 39   // (KH-1)/2
#define RW 34   // (KW-1)/2
#define TH 16   // output rows per block in K2
#define NG 64   // 8-row groups per image

__device__ float g_s8[NB * NG * WW];   // 4 MB

__device__ __forceinline__ float4 f4add(float4 a, float4 b) {
    return make_float4(a.x + b.x, a.y + b.y, a.z + b.z, a.w + b.w);
}
__device__ __forceinline__ float2 f2add(float2 a, float2 b) {
    return make_float2(a.x + b.x, a.y + b.y);
}
__device__ __forceinline__ float2 f2sub(float2 a, float2 b) {
    return make_float2(a.x - b.x, a.y - b.y);
}

// ---------------------------------------------------------------------------
// K1: 8-row group sums, float4. Grid = NB*NG/4 = 512 blocks of 512 threads.
// ---------------------------------------------------------------------------
__global__ __launch_bounds__(512) void s8_kernel(const float* __restrict__ x) {
    const int q = threadIdx.x >> 7;        // sub-group 0..3
    const int i = threadIdx.x & 127;       // float4 column
    const int g = (blockIdx.x << 2) + q;   // global group (n*NG + group)
    const float4* __restrict__ p = reinterpret_cast<const float4*>(x) + (g << 10) + i;
    float4 a = f4add(p[0 * 128], p[1 * 128]);
    float4 b = f4add(p[2 * 128], p[3 * 128]);
    a = f4add(a, p[4 * 128]);
    b = f4add(b, p[5 * 128]);
    a = f4add(a, p[6 * 128]);
    b = f4add(b, p[7 * 128]);
    reinterpret_cast<float4*>(g_s8)[(g << 7) + i] = f4add(a, b);
}

__global__ __launch_bounds__(512, 2) void sliding_mean_fused(const float* __restrict__ x,
                                                             float* __restrict__ out) {
    __shared__ float smemC[TH * WW];   // 32 KB, plain row-major

    const int blk = blockIdx.x;
    const int hc = blk & 31;           // 32 h-chunks of 16 rows
    const int n  = blk >> 5;           // batch
    const int h0 = hc * TH;
    const int t  = threadIdx.x;
    const int lane = t & 31;
    const int wrp  = t >> 5;

    const int gbase = n * (HH * WW);

    // ======================= Phase A (float2, two halves) ====================
    {
        const int halfid = t >> 8;         // 0: rows 0-7, 1: rows 8-15
        const int ht = t & 255;            // column-pair index (col = 2*ht)
        const int hb = h0 + (halfid << 3); // first row of this half

        const float2* __restrict__ xp2 =
            reinterpret_cast<const float2*>(x + gbase) + ht;          // row stride 256
        const float2* __restrict__ s8p2 =
            reinterpret_cast<const float2*>(g_s8 + (n << 15)) + ht;   // group stride 256
        float2* __restrict__ sm2 =
            reinterpret_cast<float2*>(smemC) + (halfid << 11) + ht;   // 8 rows * 256

        float2 s;
        const bool interior = (hb >= 40) && (hb <= 464);
        if (interior) {
            // ---- init: 7 x rows + 9 S8 taps (one MLP batch) ----
            const float2* __restrict__ ph = xp2 + ((hb - 39) << 8);
            float2 e0 = f2add(ph[0 << 8], ph[1 << 8]);
            float2 e1 = f2add(ph[2 << 8], ph[3 << 8]);
            float2 e2 = f2add(ph[4 << 8], ph[5 << 8]);
            float2 e3 = ph[6 << 8];
            const float2* __restrict__ pg = s8p2 + (((hb - 32) >> 3) << 8);
            float2 g0 = f2add(pg[0 << 8], pg[1 << 8]);
            float2 g1 = f2add(pg[2 << 8], pg[3 << 8]);
            float2 g2 = f2add(pg[4 << 8], pg[5 << 8]);
            float2 g3 = f2add(pg[6 << 8], pg[7 << 8]);
            float2 g4 = pg[8 << 8];
            s = f2add(f2add(f2add(e0, e1), f2add(e2, e3)),
                      f2add(f2add(f2add(g0, g1), f2add(g2, g3)), g4));

            // ---- fill: load ALL 16 row deltas as one batch, then carry ----
            const float2* __restrict__ pa = xp2 + ((hb + RH + 1) << 8);
            const float2* __restrict__ pb = xp2 + ((hb - RH) << 8);
            float2 da[8], db[8];
            #pragma unroll
            for (int k = 0; k < 8; ++k) da[k] = pa[k << 8];
            #pragma unroll
            for (int k = 0; k < 8; ++k) db[k] = pb[k << 8];
            #pragma unroll
            for (int k = 0; k < 8; ++k) {
                sm2[k << 8] = s;
                s = f2add(s, f2sub(da[k], db[k]));
            }
        } else {
            int lo = hb - RH; if (lo < 0) lo = 0;
            int hi = hb + RH; if (hi > HH - 1) hi = HH - 1;
            const int glo = (lo + 7) >> 3;
            const int ghi = (hi + 1) >> 3;
            s = make_float2(0.f, 0.f);
            for (int r = lo; r < (glo << 3); ++r) s = f2add(s, xp2[r << 8]);
            for (int g = glo; g < ghi; ++g)       s = f2add(s, s8p2[g << 8]);
            for (int r = (ghi << 3); r <= hi; ++r) s = f2add(s, xp2[r << 8]);

            #pragma unroll
            for (int k = 0; k < 8; ++k) {
                sm2[k << 8] = s;
                int add = hb + k + RH + 1;
                int sb  = hb + k - RH;
                float2 a = (add < HH) ? xp2[add << 8] : make_float2(0.f, 0.f);
                float2 b = (sb >= 0)  ? xp2[sb << 8]  : make_float2(0.f, 0.f);
                s = f2add(s, f2sub(a, b));
            }
        }
    }
    __syncthreads();

    // ---- prefetch ALL epilogue x reads (overlap the scan) -------------------
    const int rb4 = (gbase + (h0 + wrp) * WW) >> 2;   // float4 row base
    const float4* __restrict__ x4 = reinterpret_cast<const float4*>(x);
    float4* __restrict__ out4 = reinterpret_cast<float4*>(out);
    float4 xv[4];
    #pragma unroll
    for (int c = 0; c < 4; ++c) xv[c] = x4[rb4 + lane + (c << 5)];

    // ========== Phase B: per-warp block-cyclic prefix scan (registers) =======
    // lane holds P at positions 128c + 4*lane + j  ->  p[4c + j]
    const unsigned FULL = 0xffffffffu;
    const float4* __restrict__ row4 =
        reinterpret_cast<const float4*>(smemC + (wrp << 9));

    float p[16];
    #pragma unroll
    for (int c = 0; c < 4; ++c) {
        float4 v = row4[lane + (c << 5)];
        p[c * 4 + 0] = v.x; p[c * 4 + 1] = v.y; p[c * 4 + 2] = v.z; p[c * 4 + 3] = v.w;
    }
    #pragma unroll
    for (int c = 0; c < 4; ++c) {
        p[c * 4 + 1] += p[c * 4 + 0];
        p[c * 4 + 2] += p[c * 4 + 1];
        p[c * 4 + 3] += p[c * 4 + 2];
    }
    float tot0 = p[3], tot1 = p[7], tot2 = p[11], tot3 = p[15];
    float i0 = tot0, i1 = tot1, i2 = tot2, i3 = tot3;
    #pragma unroll
    for (int off = 1; off < 32; off <<= 1) {
        float u0 = __shfl_up_sync(FULL, i0, off);
        float u1 = __shfl_up_sync(FULL, i1, off);
        float u2 = __shfl_up_sync(FULL, i2, off);
        float u3 = __shfl_up_sync(FULL, i3, off);
        if (lane >= off) { i0 += u0; i1 += u1; i2 += u2; i3 += u3; }
    }
    float B0 = __shfl_sync(FULL, i0, 31);
    float B1 = __shfl_sync(FULL, i1, 31);
    float B2 = __shfl_sync(FULL, i2, 31);
    float B3 = __shfl_sync(FULL, i3, 31);
    float o0 = i0 - tot0;
    float o1 = i1 - tot1 + B0;
    float o2 = i2 - tot2 + (B0 + B1);
    float o3 = i3 - tot3 + ((B0 + B1) + B2);
    p[0] += o0;  p[1] += o0;  p[2] += o0;  p[3] += o0;
    p[4] += o1;  p[5] += o1;  p[6] += o1;  p[7] += o1;
    p[8] += o2;  p[9] += o2;  p[10] += o2; p[11] += o2;
    p[12] += o3; p[13] += o3; p[14] += o3; p[15] += o3;
    const float total = ((B0 + B1) + B2) + B3;   // = P[511]

    // ===== Epilogue: register window taps via shfl + float4 x/out ============
    //   hi = P[w+34]  (pos>511 -> total)     lo = P[w-35]  (pos<0 -> 0)
    const float inv_cnt = 1.0f / (float)(KH * KW);
    const float inv_std = 0.2f;  // 1/5

    #pragma unroll
    for (int c = 0; c < 4; ++c) {
        // hi taps: j=0,1 -> src lane+8, reg j+2 ; j=2,3 -> src lane+9, reg j-2
        float h0s = (lane >= 8) ? p[4 * c + 2] : ((c < 3) ? p[4 * c + 6] : total);
        float h1s = (lane >= 8) ? p[4 * c + 3] : ((c < 3) ? p[4 * c + 7] : total);
        float h2s = (lane >= 9) ? p[4 * c + 0] : ((c < 3) ? p[4 * c + 4] : total);
        float h3s = (lane >= 9) ? p[4 * c + 1] : ((c < 3) ? p[4 * c + 5] : total);
        float hi0 = __shfl_sync(FULL, h0s, (lane + 8) & 31);
        float hi1 = __shfl_sync(FULL, h1s, (lane + 8) & 31);
        float hi2 = __shfl_sync(FULL, h2s, (lane + 9) & 31);
        float hi3 = __shfl_sync(FULL, h3s, (lane + 9) & 31);
        // lo taps: j=0,1,2 -> src lane-9, reg j+1 ; j=3 -> src lane-8, reg 0
        float l0s = (lane >= 23) ? ((c > 0) ? p[4 * c - 3] : 0.f) : p[4 * c + 1];
        float l1s = (lane >= 23) ? ((c > 0) ? p[4 * c - 2] : 0.f) : p[4 * c + 2];
        float l2s = (lane >= 23) ? ((c > 0) ? p[4 * c - 1] : 0.f) : p[4 * c + 3];
        float l3s = (lane >= 24) ? ((c > 0) ? p[4 * c - 4] : 0.f) : p[4 * c + 0];
        float lo0 = __shfl_sync(FULL, l0s, (lane - 9) & 31);
        float lo1 = __shfl_sync(FULL, l1s, (lane - 9) & 31);
        float lo2 = __shfl_sync(FULL, l2s, (lane - 9) & 31);
        float lo3 = __shfl_sync(FULL, l3s, (lane - 8) & 31);

        float4 r;
        r.x = (xv[c].x - (hi0 - lo0) * inv_cnt) * inv_std;
        r.y = (xv[c].y - (hi1 - lo1) * inv_cnt) * inv_std;
        r.z = (xv[c].z - (hi2 - lo2) * inv_cnt) * inv_std;
        r.w = (xv[c].w - (hi3 - lo3) * inv_cnt) * inv_std;
        __stcs(&out4[rb4 + lane + (c << 5)], r);
    }
}

extern "C" void kernel_launch(void* const* d_in, const int* in_sizes, int n_in,
                              void* d_out, int out_size) {
    const float* x = (const float*)d_in[0];
    float* out = (float*)d_out;

    s8_kernel<<<NB * NG / 4, 512>>>(x);
    sliding_mean_fused<<<NB * (HH / TH), 512>>>(x, out);
}